// round 4
// baseline (speedup 1.0000x reference)
#include <cuda_runtime.h>
#include <cstdint>

#define IN_DIM  256
#define OUT_DIM 128
#define MAXN    100000

// ---------------- device scratch (no runtime allocation allowed) ----------------
__device__ float g_Wc[OUT_DIM * IN_DIM];                 // combined weight Wg@Wp  [128,256]
__device__ float g_g[(size_t)MAXN * OUT_DIM];            // g[i] = dinv[i] * (x[i] @ Wc^T)
__device__ int   g_deg[MAXN];
__device__ float g_dinv[MAXN];
__device__ int   g_is64;

// ---------------- dtype detection for edge_index (int32 vs int64) ----------------
__global__ void k_detect(const unsigned* __restrict__ w, long long E) {
    if (threadIdx.x == 0 && blockIdx.x == 0) {
        int is64 = 1;
        for (int i = 0; i < 32; i++) {
            long long e = (E > 1) ? ((E - 1) * (long long)i) / 31 : 0;
            // only touches first 2E 32-bit words -> in bounds for both dtypes
            if (w[2 * e + 1] != 0u) { is64 = 0; break; }
        }
        g_is64 = is64;
    }
}

__global__ void k_zero_deg(int n) {
    int i = blockIdx.x * blockDim.x + threadIdx.x;
    if (i < n) g_deg[i] = 0;
}

__global__ void k_count(const void* __restrict__ ei, long long E) {
    long long e = blockIdx.x * (long long)blockDim.x + threadIdx.x;
    if (e >= E) return;
    int c;
    if (g_is64) c = (int)((const long long*)ei)[e + E];
    else        c = ((const int*)ei)[e + E];
    atomicAdd(&g_deg[c], 1);
}

__global__ void k_dinv(int n) {
    int i = blockIdx.x * blockDim.x + threadIdx.x;
    if (i < n) g_dinv[i] = rsqrtf((float)(g_deg[i] + 1));  // +1 self loop; always > 0
}

// ---------------- Wc = Wg @ Wp  [128,256] ----------------
__global__ void k_wc(const float* __restrict__ Wg, const float* __restrict__ Wp) {
    int o = blockIdx.x;       // 0..127
    int k = threadIdx.x;      // 0..255
    float s = 0.f;
#pragma unroll 8
    for (int j = 0; j < OUT_DIM; j++)
        s += Wg[o * OUT_DIM + j] * Wp[j * IN_DIM + k];
    g_Wc[o * IN_DIM + k] = s;
}

// ---------------- packed fp32x2 FMA helpers (Blackwell-only PTX path) ----------------
__device__ __forceinline__ void ffma2(unsigned long long& d, unsigned long long a, unsigned long long b) {
    asm("fma.rn.f32x2 %0, %1, %2, %0;" : "+l"(d) : "l"(a), "l"(b));
}
__device__ __forceinline__ unsigned long long splat2(float x) {
    unsigned long long r; unsigned xi = __float_as_uint(x);
    asm("mov.b64 %0, {%1, %1};" : "=l"(r) : "r"(xi));
    return r;
}

// ---------------- GEMM: g[i] = dinv[i]*(x[i] @ Wc^T), also seeds out accumulator ----------------
// 128x128 tile (BN=128 == full OUT_DIM), BK=16, 256 threads, 8x8 per thread via fma.rn.f32x2
__global__ void __launch_bounds__(256) k_gemm(const float* __restrict__ A, int N,
                                              float* __restrict__ out) {
    __shared__ float As[16][132];
    __shared__ float Bs[16][132];
    const int tid = threadIdx.x;
    const int tx = tid & 15;      // out-feature group
    const int ty = tid >> 4;      // row group
    const int r0 = blockIdx.x * 128;

    unsigned long long acc2[8][4];
#pragma unroll
    for (int i = 0; i < 8; i++)
#pragma unroll
        for (int j = 0; j < 4; j++) acc2[i][j] = 0ull;

    for (int kt = 0; kt < IN_DIM; kt += 16) {
#pragma unroll
        for (int l = 0; l < 2; l++) {
            int q  = tid + l * 256;     // 0..511 float4 slots
            int r  = q >> 2;            // 0..127
            int kq = q & 3;
            int gr = r0 + r;
            float4 va = make_float4(0.f, 0.f, 0.f, 0.f);
            if (gr < N) va = *(const float4*)(A + (size_t)gr * IN_DIM + kt + kq * 4);
            As[kq * 4 + 0][r] = va.x; As[kq * 4 + 1][r] = va.y;
            As[kq * 4 + 2][r] = va.z; As[kq * 4 + 3][r] = va.w;
            float4 vb = *(const float4*)(g_Wc + r * IN_DIM + kt + kq * 4);
            Bs[kq * 4 + 0][r] = vb.x; Bs[kq * 4 + 1][r] = vb.y;
            Bs[kq * 4 + 2][r] = vb.z; Bs[kq * 4 + 3][r] = vb.w;
        }
        __syncthreads();
#pragma unroll
        for (int kk = 0; kk < 16; kk++) {
            float a[8];
            *(float4*)(a)     = *(const float4*)&As[kk][ty * 8];
            *(float4*)(a + 4) = *(const float4*)&As[kk][ty * 8 + 4];
            unsigned long long b2[4];
            *(uint4*)(&b2[0]) = *(const uint4*)&Bs[kk][tx * 8];
            *(uint4*)(&b2[2]) = *(const uint4*)&Bs[kk][tx * 8 + 4];
#pragma unroll
            for (int i = 0; i < 8; i++) {
                unsigned long long ai = splat2(a[i]);
#pragma unroll
                for (int j = 0; j < 4; j++) ffma2(acc2[i][j], ai, b2[j]);
            }
        }
        __syncthreads();
    }

    // epilogue: scale by dinv, write g and seed out accumulator
#pragma unroll
    for (int i = 0; i < 8; i++) {
        int r = r0 + ty * 8 + i;
        if (r >= N) break;
        float di = g_dinv[r];
        const float* accf = (const float*)acc2[i];
        float4 v0, v1;
        v0.x = accf[0] * di; v0.y = accf[1] * di; v0.z = accf[2] * di; v0.w = accf[3] * di;
        v1.x = accf[4] * di; v1.y = accf[5] * di; v1.z = accf[6] * di; v1.w = accf[7] * di;
        size_t base = (size_t)r * OUT_DIM + tx * 8;
        *(float4*)(g_g + base)     = v0;
        *(float4*)(g_g + base + 4) = v1;
        *(float4*)(out + base)     = v0;
        *(float4*)(out + base + 4) = v1;
    }
}

// ---------------- edge scatter: out[col] += g[row] ----------------
// One warp per edge: lanes broadcast-load the (row,col) pair, then lane k moves
// float4 chunk k (k=0..31 -> all 128 features). Fully coalesced gather + red.
__global__ void k_edges(const void* __restrict__ ei, long long E, float* __restrict__ out) {
    long long idx = blockIdx.x * (long long)blockDim.x + threadIdx.x;
    if (idx >= E * 32) return;
    long long e = idx >> 5;
    int k = (int)(idx & 31);
    int r, c;
    if (g_is64) {
        const long long* p = (const long long*)ei;
        r = (int)p[e]; c = (int)p[e + E];
    } else {
        const int* p = (const int*)ei;
        r = p[e]; c = p[e + E];
    }
    float4 v = *(const float4*)(g_g + (size_t)r * OUT_DIM + k * 4);
    float* dst = out + (size_t)c * OUT_DIM + k * 4;
    asm volatile("red.global.add.v4.f32 [%0], {%1,%2,%3,%4};"
                 :: "l"(dst), "f"(v.x), "f"(v.y), "f"(v.z), "f"(v.w) : "memory");
}

// ---------------- finalize: out = normalize(dinv*acc + bg) ----------------
__global__ void k_final(float* __restrict__ out, const float* __restrict__ bg, int N) {
    int warp = (blockIdx.x * blockDim.x + threadIdx.x) >> 5;
    int lane = threadIdx.x & 31;
    if (warp >= N) return;
    float di = g_dinv[warp];
    size_t base = (size_t)warp * OUT_DIM + lane * 4;
    float4 v = *(float4*)(out + base);
    float4 b = *(const float4*)(bg + lane * 4);
    v.x = v.x * di + b.x; v.y = v.y * di + b.y;
    v.z = v.z * di + b.z; v.w = v.w * di + b.w;
    float s = v.x * v.x + v.y * v.y + v.z * v.z + v.w * v.w;
#pragma unroll
    for (int off = 16; off > 0; off >>= 1) s += __shfl_xor_sync(0xffffffffu, s, off);
    float scale = 1.0f / fmaxf(sqrtf(s), 1e-12f);
    v.x *= scale; v.y *= scale; v.z *= scale; v.w *= scale;
    *(float4*)(out + base) = v;
}

extern "C" void kernel_launch(void* const* d_in, const int* in_sizes, int n_in,
                              void* d_out, int out_size) {
    const float* x  = (const float*)d_in[0];
    const void*  ei = d_in[1];
    const float* Wp = (const float*)d_in[2];
    const float* Wg = (const float*)d_in[3];
    const float* bg = (const float*)d_in[4];
    float* out = (float*)d_out;

    int N = in_sizes[0] / IN_DIM;
    long long E = (long long)in_sizes[1] / 2;

    k_detect<<<1, 1>>>((const unsigned*)ei, E);
    k_zero_deg<<<(N + 255) / 256, 256>>>(N);
    k_count<<<(int)((E + 255) / 256), 256>>>(ei, E);
    k_dinv<<<(N + 255) / 256, 256>>>(N);
    k_wc<<<OUT_DIM, IN_DIM>>>(Wg, Wp);
    k_gemm<<<(N + 127) / 128, 256>>>(x, N, out);
    long long tot = E * 32;
    k_edges<<<(int)((tot + 255) / 256), 256>>>(ei, E, out);
    k_final<<<(N + 7) / 8, 256>>>(out, bg, N);
}

// round 6
// speedup vs baseline: 1.4779x; 1.4779x over previous
#include <cuda_runtime.h>
#include <cstdint>

#define IN_DIM  256
#define OUT_DIM 128
#define MAXN    100000
#define MAXE    1700000

// ---------------- device scratch ----------------
__device__ float g_Wc[OUT_DIM * IN_DIM];                 // combined weight Wg@Wp  [128,256]
__device__ float g_g[(size_t)MAXN * OUT_DIM];            // g[i] = dinv[i] * (x[i] @ Wc^T)
__device__ int   g_deg[MAXN];
__device__ float g_dinv[MAXN];
__device__ int   g_start[MAXN];
__device__ int   g_head[MAXN];
__device__ int   g_bsum[(MAXN + 1023) / 1024 + 1];
__device__ int   g_srow[MAXE];
__device__ int   g_is64;

// ---------------- dtype detection for edge_index (int32 vs int64) ----------------
__global__ void k_detect(const unsigned* __restrict__ w, long long E) {
    if (threadIdx.x == 0 && blockIdx.x == 0) {
        int is64 = 1;
        for (int i = 0; i < 32; i++) {
            long long e = (E > 1) ? ((E - 1) * (long long)i) / 31 : 0;
            if (w[2 * e + 1] != 0u) { is64 = 0; break; }
        }
        g_is64 = is64;
    }
}

__global__ void k_zero_deg(int n) {
    int i = blockIdx.x * blockDim.x + threadIdx.x;
    if (i < n) g_deg[i] = 0;
}

__global__ void k_count(const void* __restrict__ ei, long long E) {
    long long e = blockIdx.x * (long long)blockDim.x + threadIdx.x;
    if (e >= E) return;
    int c;
    if (g_is64) c = (int)((const long long*)ei)[e + E];
    else        c = ((const int*)ei)[e + E];
    atomicAdd(&g_deg[c], 1);
}

__global__ void k_dinv(int n) {
    int i = blockIdx.x * blockDim.x + threadIdx.x;
    if (i < n) g_dinv[i] = rsqrtf((float)(g_deg[i] + 1));   // +1 self loop
}

// ---------------- exclusive scan of deg -> start (3 tiny kernels) ----------------
__global__ void k_scan1(int n) {                 // block = 1024
    __shared__ int sh[1024];
    int i = blockIdx.x * 1024 + threadIdx.x;
    int v = (i < n) ? g_deg[i] : 0;
    sh[threadIdx.x] = v;
    __syncthreads();
#pragma unroll
    for (int off = 1; off < 1024; off <<= 1) {
        int t = (threadIdx.x >= off) ? sh[threadIdx.x - off] : 0;
        __syncthreads();
        sh[threadIdx.x] += t;
        __syncthreads();
    }
    if (i < n) g_start[i] = sh[threadIdx.x] - v;        // exclusive within block
    if (threadIdx.x == 1023) g_bsum[blockIdx.x] = sh[1023];
}

__global__ void k_scan2(int nb) {                // 1 thread, nb ~ 98
    if (threadIdx.x == 0 && blockIdx.x == 0) {
        int run = 0;
        for (int b = 0; b < nb; b++) { int t = g_bsum[b]; g_bsum[b] = run; run += t; }
    }
}

__global__ void k_scan3(int n) {
    int i = blockIdx.x * blockDim.x + threadIdx.x;
    if (i < n) {
        int s = g_start[i] + g_bsum[i >> 10];
        g_start[i] = s;
        g_head[i]  = s;                           // scatter cursor
    }
}

// ---------------- bucket edges by target: srow[pos] = row ----------------
__global__ void k_scatter(const void* __restrict__ ei, long long E) {
    long long e = blockIdx.x * (long long)blockDim.x + threadIdx.x;
    if (e >= E) return;
    int r, c;
    if (g_is64) {
        const long long* p = (const long long*)ei;
        r = (int)p[e]; c = (int)p[e + E];
    } else {
        const int* p = (const int*)ei;
        r = p[e]; c = p[e + E];
    }
    int pos = atomicAdd(&g_head[c], 1);
    g_srow[pos] = r;
}

// ---------------- Wc = Wg @ Wp  [128,256] ----------------
__global__ void k_wc(const float* __restrict__ Wg, const float* __restrict__ Wp) {
    int o = blockIdx.x;
    int k = threadIdx.x;
    float s = 0.f;
#pragma unroll 8
    for (int j = 0; j < OUT_DIM; j++)
        s += Wg[o * OUT_DIM + j] * Wp[j * IN_DIM + k];
    g_Wc[o * IN_DIM + k] = s;
}

// ---------------- packed fp32x2 FMA helpers ----------------
__device__ __forceinline__ void ffma2(unsigned long long& d, unsigned long long a, unsigned long long b) {
    asm("fma.rn.f32x2 %0, %1, %2, %0;" : "+l"(d) : "l"(a), "l"(b));
}
__device__ __forceinline__ unsigned long long splat2(float x) {
    unsigned long long r; unsigned xi = __float_as_uint(x);
    asm("mov.b64 %0, {%1, %1};" : "=l"(r) : "r"(xi));
    return r;
}

// ---------------- GEMM: g[i] = dinv[i]*(x[i] @ Wc^T) ----------------
__global__ void __launch_bounds__(256) k_gemm(const float* __restrict__ A, int N) {
    __shared__ float As[16][132];
    __shared__ float Bs[16][132];
    const int tid = threadIdx.x;
    const int tx = tid & 15;
    const int ty = tid >> 4;
    const int r0 = blockIdx.x * 128;

    unsigned long long acc2[8][4];
#pragma unroll
    for (int i = 0; i < 8; i++)
#pragma unroll
        for (int j = 0; j < 4; j++) acc2[i][j] = 0ull;

    for (int kt = 0; kt < IN_DIM; kt += 16) {
#pragma unroll
        for (int l = 0; l < 2; l++) {
            int q  = tid + l * 256;
            int r  = q >> 2;
            int kq = q & 3;
            int gr = r0 + r;
            float4 va = make_float4(0.f, 0.f, 0.f, 0.f);
            if (gr < N) va = *(const float4*)(A + (size_t)gr * IN_DIM + kt + kq * 4);
            As[kq * 4 + 0][r] = va.x; As[kq * 4 + 1][r] = va.y;
            As[kq * 4 + 2][r] = va.z; As[kq * 4 + 3][r] = va.w;
            float4 vb = *(const float4*)(g_Wc + r * IN_DIM + kt + kq * 4);
            Bs[kq * 4 + 0][r] = vb.x; Bs[kq * 4 + 1][r] = vb.y;
            Bs[kq * 4 + 2][r] = vb.z; Bs[kq * 4 + 3][r] = vb.w;
        }
        __syncthreads();
#pragma unroll
        for (int kk = 0; kk < 16; kk++) {
            float a[8];
            *(float4*)(a)     = *(const float4*)&As[kk][ty * 8];
            *(float4*)(a + 4) = *(const float4*)&As[kk][ty * 8 + 4];
            unsigned long long b2[4];
            *(uint4*)(&b2[0]) = *(const uint4*)&Bs[kk][tx * 8];
            *(uint4*)(&b2[2]) = *(const uint4*)&Bs[kk][tx * 8 + 4];
#pragma unroll
            for (int i = 0; i < 8; i++) {
                unsigned long long ai = splat2(a[i]);
#pragma unroll
                for (int j = 0; j < 4; j++) ffma2(acc2[i][j], ai, b2[j]);
            }
        }
        __syncthreads();
    }

#pragma unroll
    for (int i = 0; i < 8; i++) {
        int r = r0 + ty * 8 + i;
        if (r >= N) break;
        float di = g_dinv[r];
        const float* accf = (const float*)acc2[i];
        float4 v0, v1;
        v0.x = accf[0] * di; v0.y = accf[1] * di; v0.z = accf[2] * di; v0.w = accf[3] * di;
        v1.x = accf[4] * di; v1.y = accf[5] * di; v1.z = accf[6] * di; v1.w = accf[7] * di;
        size_t base = (size_t)r * OUT_DIM + tx * 8;
        *(float4*)(g_g + base)     = v0;
        *(float4*)(g_g + base + 4) = v1;
    }
}

// ---------------- fused gather + finalize: one warp per node ----------------
// acc = g[c] (self loop) + sum over segment of g[srow[j]]; then
// out[c] = normalize(acc*dinv[c] + bg)
__global__ void __launch_bounds__(256) k_gather(float* __restrict__ out,
                                                const float* __restrict__ bg, int N) {
    int c = (int)((blockIdx.x * (long long)blockDim.x + threadIdx.x) >> 5);
    int lane = threadIdx.x & 31;
    if (c >= N) return;

    size_t fb = (size_t)c * OUT_DIM + lane * 4;
    float4 acc = *(const float4*)(g_g + fb);       // self loop term

    int s = g_start[c];
    int d = g_deg[c];
    const int* rp = g_srow + s;

    int j = 0;
    for (; j + 2 <= d; j += 2) {                   // 2-edge pipeline for MLP
        int r0 = rp[j], r1 = rp[j + 1];
        float4 v0 = *(const float4*)(g_g + (size_t)r0 * OUT_DIM + lane * 4);
        float4 v1 = *(const float4*)(g_g + (size_t)r1 * OUT_DIM + lane * 4);
        acc.x += v0.x; acc.y += v0.y; acc.z += v0.z; acc.w += v0.w;
        acc.x += v1.x; acc.y += v1.y; acc.z += v1.z; acc.w += v1.w;
    }
    if (j < d) {
        int r0 = rp[j];
        float4 v0 = *(const float4*)(g_g + (size_t)r0 * OUT_DIM + lane * 4);
        acc.x += v0.x; acc.y += v0.y; acc.z += v0.z; acc.w += v0.w;
    }

    float di = g_dinv[c];
    float4 b = *(const float4*)(bg + lane * 4);
    float4 v;
    v.x = acc.x * di + b.x; v.y = acc.y * di + b.y;
    v.z = acc.z * di + b.z; v.w = acc.w * di + b.w;

    float ss = v.x * v.x + v.y * v.y + v.z * v.z + v.w * v.w;
#pragma unroll
    for (int off = 16; off > 0; off >>= 1) ss += __shfl_xor_sync(0xffffffffu, ss, off);
    float scale = 1.0f / fmaxf(sqrtf(ss), 1e-12f);
    v.x *= scale; v.y *= scale; v.z *= scale; v.w *= scale;
    *(float4*)(out + fb) = v;
}

extern "C" void kernel_launch(void* const* d_in, const int* in_sizes, int n_in,
                              void* d_out, int out_size) {
    const float* x  = (const float*)d_in[0];
    const void*  ei = d_in[1];
    const float* Wp = (const float*)d_in[2];
    const float* Wg = (const float*)d_in[3];
    const float* bg = (const float*)d_in[4];
    float* out = (float*)d_out;

    int N = in_sizes[0] / IN_DIM;
    long long E = (long long)in_sizes[1] / 2;
    int nb = (N + 1023) / 1024;

    k_detect<<<1, 1>>>((const unsigned*)ei, E);
    k_zero_deg<<<(N + 255) / 256, 256>>>(N);
    k_count<<<(int)((E + 255) / 256), 256>>>(ei, E);
    k_dinv<<<(N + 255) / 256, 256>>>(N);
    k_scan1<<<nb, 1024>>>(N);
    k_scan2<<<1, 32>>>(nb);
    k_scan3<<<(N + 255) / 256, 256>>>(N);
    k_scatter<<<(int)((E + 255) / 256), 256>>>(ei, E);
    k_wc<<<OUT_DIM, IN_DIM>>>(Wg, Wp);
    k_gemm<<<(N + 127) / 128, 256>>>(x, N);
    k_gather<<<(N * 32 + 255) / 256, 256>>>(out, bg, N);
}